// round 9
// baseline (speedup 1.0000x reference)
#include <cuda_runtime.h>
#include <cstdint>
#include <cstddef>

// Problem dims
#define TT 700
#define BB 64
#define UU 400
#define GG 1600   // 4*U
#define FF 3
#define NCTA 148
#define NSTEPS 702   // wavefront steps: L0@s, L1@s-1, L2@s-2
#define NJOBS 500    // 100 L0 jobs (4 units) + 200 L1 + 200 L2 (2 units each)

typedef unsigned long long ull;

// ---------------- static device scratch -------------------------------------
__device__ float g_xp[(size_t)TT * GG * BB];    // layer0 input projection [t][col][b]
__device__ float g_h0[(size_t)TT * UU * BB];    // [t][u][b]
__device__ float g_h1[(size_t)TT * UU * BB];
__device__ float g_h2[(size_t)TT * UU * BB];
__device__ unsigned g_flags[NCTA];              // zero-init, monotonic barrier counters

// ---------------- helpers ----------------------------------------------------
__device__ __forceinline__ unsigned ld_acq(const unsigned* p) {
    unsigned v;
    asm volatile("ld.acquire.gpu.u32 %0, [%1];" : "=r"(v) : "l"(p) : "memory");
    return v;
}
__device__ __forceinline__ void st_rel(unsigned* p, unsigned v) {
    asm volatile("st.release.gpu.u32 [%0], %1;" :: "l"(p), "r"(v) : "memory");
}
__device__ __forceinline__ void ffma2(ull& d, ull a, ull b) {
    asm("fma.rn.f32x2 %0, %1, %2, %0;" : "+l"(d) : "l"(a), "l"(b));
}
__device__ __forceinline__ ull dup2(float w) {
    ull r; asm("mov.b64 %0, {%1, %1};" : "=l"(r) : "f"(w)); return r;
}
__device__ __forceinline__ ull pack2(float lo, float hi) {
    ull r; asm("mov.b64 %0, {%1, %2};" : "=l"(r) : "f"(lo), "f"(hi)); return r;
}
__device__ __forceinline__ float f2lo(ull v){ return __int_as_float((int)(unsigned)v); }
__device__ __forceinline__ float f2hi(ull v){ return __int_as_float((int)(v >> 32)); }
__device__ __forceinline__ float sigm(float x) { return 1.0f / (1.0f + __expf(-x)); }

// ---------------- layer-0 input projection (K = F = 3) -----------------------
__global__ void xp_l0_kernel(const float* __restrict__ x,
                             const float* __restrict__ Wx0,
                             const float* __restrict__ b0)
{
    int t = blockIdx.x;
    __shared__ float xs[BB * FF];
    __shared__ float ws[FF * GG];
    __shared__ float bs[GG];
    int tid = threadIdx.x;
    if (tid < BB * FF) {
        int b = tid / FF, d = tid % FF;
        xs[tid] = x[(size_t)b * (TT * FF) + t * FF + d];
    }
    for (int i = tid; i < FF * GG; i += 256) ws[i] = Wx0[i];
    for (int i = tid; i < GG; i += 256) bs[i] = b0[i];
    __syncthreads();
    float* dst = g_xp + (size_t)t * GG * BB;
    for (int idx = tid; idx < GG * BB; idx += 256) {
        int col = idx >> 6, b = idx & 63;
        float v = bs[col]
                + xs[b * 3 + 0] * ws[col]
                + xs[b * 3 + 1] * ws[GG + col]
                + xs[b * 3 + 2] * ws[2 * GG + col];
        dst[idx] = v;
    }
}

// ---------------- fused 3-layer wavefront scan --------------------------------
// 148 CTAs x 256 threads, persistent, 702 steps, one grid barrier per step.
// Warp-job: jid = wid*148 + cta (wid<4, jid<500):
//   jid <100 : L0 job, 4 units (4*jid..+3), two 400-row phases over h0[t-1]
//   jid <300 : L1 job, 2 units, phase0 = Wx1 over h0[t], phase1 = Wh1 over h1[t-1]
//   else     : L2 job, 2 units, phase0 = Wx2 over h1[t], phase1 = Wh2 over h2[t-1]
// Thread = (2 units, batch-pair): gates + c-state fully register-resident.
// Weights pre-duplicated as f32x2 pairs in smem: [warp][800 rows][8 ull].
#define WAVE_SMEM (4 * 800 * 8 * 8)   // 204800 B

// accumulate 400 rows: acc[ul][g] += h[r] * w[r][ul*4+g]
__device__ __forceinline__ void accum400(ull (&acc)[2][4],
                                         const ull* __restrict__ wp,
                                         const float* __restrict__ src,
                                         int lane)
{
    const char* hp = (const char*)(src + lane * 2);
    ull h[8], hn[8];
#pragma unroll
    for (int j = 0; j < 8; j++) h[j] = *(const ull*)(hp + j * (BB * 4));
#pragma unroll 1
    for (int r = 0; r < 400; r += 8) {
        if (r + 8 < 400) {
#pragma unroll
            for (int j = 0; j < 8; j++)
                hn[j] = *(const ull*)(hp + (r + 8 + j) * (BB * 4));
        }
#pragma unroll
        for (int j = 0; j < 8; j++) {
            const ull* w = wp + (size_t)(r + j) * 8;
            ulonglong2 wA = *(const ulonglong2*)(w);
            ulonglong2 wB = *(const ulonglong2*)(w + 2);
            ulonglong2 wC = *(const ulonglong2*)(w + 4);
            ulonglong2 wD = *(const ulonglong2*)(w + 6);
            ffma2(acc[0][0], h[j], wA.x); ffma2(acc[0][1], h[j], wA.y);
            ffma2(acc[0][2], h[j], wB.x); ffma2(acc[0][3], h[j], wB.y);
            ffma2(acc[1][0], h[j], wC.x); ffma2(acc[1][1], h[j], wC.y);
            ffma2(acc[1][2], h[j], wD.x); ffma2(acc[1][3], h[j], wD.y);
        }
#pragma unroll
        for (int j = 0; j < 8; j++) h[j] = hn[j];
    }
}

// LSTM cell for one unit, two batches; z packed f32x2 per gate; c in-place.
__device__ __forceinline__ void cell2(const ull z[4], float& c0, float& c1,
                                      float piv, float pfv, float pov,
                                      float* __restrict__ outp)
{
    float zi0 = f2lo(z[0]), zi1 = f2hi(z[0]);
    float zf0 = f2lo(z[1]), zf1 = f2hi(z[1]);
    float zg0 = f2lo(z[2]), zg1 = f2hi(z[2]);
    float zo0 = f2lo(z[3]), zo1 = f2hi(z[3]);

    float i0 = sigm(zi0 + piv * c0);
    float f0 = sigm(zf0 + pfv * c0);
    float cn0 = f0 * c0 + i0 * tanhf(zg0);
    float o0 = sigm(zo0 + pov * cn0);
    float h0 = o0 * tanhf(cn0);
    c0 = cn0;

    float i1 = sigm(zi1 + piv * c1);
    float f1 = sigm(zf1 + pfv * c1);
    float cn1 = f1 * c1 + i1 * tanhf(zg1);
    float o1 = sigm(zo1 + pov * cn1);
    float h1 = o1 * tanhf(cn1);
    c1 = cn1;

    *(ull*)outp = pack2(h0, h1);
}

__global__ void __launch_bounds__(256, 1) wave_kernel(const float* __restrict__ Wx1,
                                                      const float* __restrict__ Wx2,
                                                      const float* __restrict__ Wh,
                                                      const float* __restrict__ bb,
                                                      const float* __restrict__ pi,
                                                      const float* __restrict__ pf,
                                                      const float* __restrict__ po)
{
    extern __shared__ ull wsm[];   // [4][800][8]

    const int tid  = threadIdx.x;
    const int cta  = blockIdx.x;
    const int wid  = tid >> 5;
    const int lane = tid & 31;

    const int jid   = wid * NCTA + cta;
    const bool valid = (wid < 4) && (jid < NJOBS);

    int jtype = 0, ubase = 0;
    if (valid) {
        if (jid < 100)      { jtype = 0; ubase = 4 * jid; }
        else if (jid < 300) { jtype = 1; ubase = 2 * (jid - 100); }
        else                { jtype = 2; ubase = 2 * (jid - 300); }
    }

    // ---- fill this warp's weight region (pre-duplicated f32x2 pairs) ----
    if (valid) {
        ull* wbase = wsm + (size_t)wid * 6400;
        const float* Wh0 = Wh;
        const float* Wh1 = Wh + (size_t)UU * GG;
        const float* Wh2 = Wh + (size_t)2 * UU * GG;
        for (int idx = lane; idx < 6400; idx += 32) {
            int r  = idx >> 3;
            int s  = idx & 7;
            int ul = s >> 2;
            int g  = s & 3;
            int k  = (r < 400) ? r : r - 400;
            const float* W;
            int u;
            if (jtype == 0) {
                u = ubase + ((r < 400) ? ul : 2 + ul);
                W = Wh0;
            } else if (jtype == 1) {
                u = ubase + ul;
                W = (r < 400) ? Wx1 : Wh1;
            } else {
                u = ubase + ul;
                W = (r < 400) ? Wx2 : Wh2;
            }
            wbase[idx] = dup2(W[(size_t)k * GG + g * UU + u]);
        }
    }

    // ---- per-thread constants: bias, peepholes, c-state ----
    float bz_r[4][4];                 // [unit-local][gate]
    float pi_r[4], pf_r[4], po_r[4];
    float cst[4][2];                  // c per unit-local per batch
    const int nunits = (jtype == 0) ? 4 : 2;
    if (valid) {
        for (int ul = 0; ul < nunits; ul++) {
            int u = ubase + ul;
            pi_r[ul] = pi[jtype * UU + u];
            pf_r[ul] = pf[jtype * UU + u];
            po_r[ul] = po[jtype * UU + u];
            for (int g = 0; g < 4; g++)
                bz_r[ul][g] = bb[jtype * GG + g * UU + u];
            cst[ul][0] = 0.f; cst[ul][1] = 0.f;
        }
    }

    const unsigned base = g_flags[cta];
    __syncthreads();   // wsm ready (each warp reads only its own region, but cheap)

    const ull* mywp = wsm + (size_t)wid * 6400;

    for (int s = 0; s < NSTEPS; s++) {
        if (valid) {
            const int t = s - jtype;   // layer l computes timestep t = s - l
            if (t >= 0 && t < TT) {
                if (jtype == 0) {
                    // ---- layer 0: two phases of 2 units over h0[t-1] ----
                    const float* hrec = g_h0 + (size_t)(t - 1) * UU * BB;
                    float* hout = g_h0 + (size_t)t * UU * BB;
#pragma unroll
                    for (int p = 0; p < 2; p++) {
                        ull acc[2][4];
#pragma unroll
                        for (int ul = 0; ul < 2; ul++) {
                            int u = ubase + 2 * p + ul;
#pragma unroll
                            for (int g = 0; g < 4; g++)
                                acc[ul][g] = *(const ull*)(g_xp +
                                    ((size_t)t * GG + g * UU + u) * BB + lane * 2);
                        }
                        if (t > 0)
                            accum400(acc, mywp + p * 3200, hrec, lane);
#pragma unroll
                        for (int ul = 0; ul < 2; ul++) {
                            int q = 2 * p + ul;
                            cell2(acc[ul], cst[q][0], cst[q][1],
                                  pi_r[q], pf_r[q], po_r[q],
                                  hout + (size_t)(ubase + q) * BB + lane * 2);
                        }
                    }
                } else {
                    // ---- layers 1/2: xp-part (h_{l-1}[t]) + rec (h_l[t-1]) ----
                    const float* hin  = (jtype == 1) ? (g_h0 + (size_t)t * UU * BB)
                                                     : (g_h1 + (size_t)t * UU * BB);
                    const float* hrec = (jtype == 1) ? (g_h1 + (size_t)(t - 1) * UU * BB)
                                                     : (g_h2 + (size_t)(t - 1) * UU * BB);
                    float* hout = ((jtype == 1) ? g_h1 : g_h2) + (size_t)t * UU * BB;

                    ull acc[2][4];
#pragma unroll
                    for (int ul = 0; ul < 2; ul++)
#pragma unroll
                        for (int g = 0; g < 4; g++)
                            acc[ul][g] = dup2(bz_r[ul][g]);

                    accum400(acc, mywp, hin, lane);
                    if (t > 0)
                        accum400(acc, mywp + 3200, hrec, lane);

#pragma unroll
                    for (int ul = 0; ul < 2; ul++)
                        cell2(acc[ul], cst[ul][0], cst[ul][1],
                              pi_r[ul], pf_r[ul], po_r[ul],
                              hout + (size_t)(ubase + ul) * BB + lane * 2);
                }
            }
        }

        if (s < NSTEPS - 1) {
            __syncthreads();   // all CTA stores done (CTA scope)
            unsigned tgt = base + (unsigned)s + 1u;
            if (tid == 0) st_rel(&g_flags[cta], tgt);   // cumulative release publishes CTA stores
            if (tid < 32) {
                for (;;) {
                    bool ok = true;
                    for (int i = lane; i < NCTA; i += 32)
                        if (ld_acq(&g_flags[i]) < tgt) ok = false;
                    if (__all_sync(0xffffffffu, ok)) break;
                    __nanosleep(32);
                }
            }
            __syncthreads();   // release all warps into next step
        }
    }
}

// ---------------- final projection ------------------------------------------
// out[b][t][f] = bd[f] + sum_u h2[t][u][b] * Wd[u][f]
__global__ void final_kernel(const float* __restrict__ Wd,
                             const float* __restrict__ bd,
                             float* __restrict__ out)
{
    int t = blockIdx.x;
    int tid = threadIdx.x;  // 192
    __shared__ float wds[UU * FF];
    for (int i = tid; i < UU * FF; i += 192) wds[i] = Wd[i];
    __syncthreads();
    int b = tid / FF, f = tid % FF;
    const float* h = g_h2 + (size_t)t * UU * BB;
    float acc = bd[f];
#pragma unroll 4
    for (int u = 0; u < UU; u++)
        acc += h[(size_t)u * BB + b] * wds[u * FF + f];
    out[(size_t)b * (TT * FF) + t * FF + f] = acc;
}

// ---------------- launch -----------------------------------------------------
extern "C" void kernel_launch(void* const* d_in, const int* in_sizes, int n_in,
                              void* d_out, int out_size)
{
    (void)in_sizes; (void)n_in; (void)out_size;
    const float* x   = (const float*)d_in[0];
    const float* Wx0 = (const float*)d_in[1];
    const float* Wx1 = (const float*)d_in[2];
    const float* Wx2 = (const float*)d_in[3];
    const float* Wh  = (const float*)d_in[4];
    const float* bb  = (const float*)d_in[5];
    const float* pi  = (const float*)d_in[6];
    const float* pf  = (const float*)d_in[7];
    const float* po  = (const float*)d_in[8];
    const float* Wd  = (const float*)d_in[9];
    const float* bd  = (const float*)d_in[10];
    float* out = (float*)d_out;

    cudaFuncSetAttribute(wave_kernel, cudaFuncAttributeMaxDynamicSharedMemorySize, WAVE_SMEM);

    // layer-0 input projection (K=3, cheap, fully parallel over t)
    xp_l0_kernel<<<TT, 256>>>(x, Wx0, bb);
    // fused 3-layer wavefront (702 steps, one grid barrier per step)
    wave_kernel<<<NCTA, 256, WAVE_SMEM>>>(Wx1, Wx2, Wh, bb, pi, pf, po);
    // output projection
    final_kernel<<<TT, 192>>>(Wd, bd, out);
}

// round 10
// speedup vs baseline: 1.6721x; 1.6721x over previous
#include <cuda_runtime.h>
#include <cstdint>
#include <cstddef>

// Problem dims
#define TT 700
#define BB 64
#define UU 400
#define GG 1600   // 4*U
#define FF 3
#define NCTA 148
#define NSTEPS 702   // wavefront: L0@s, L1@s-1, L2@s-2

typedef unsigned long long ull;

// ---------------- static device scratch -------------------------------------
__device__ float g_xp[(size_t)TT * GG * BB];    // layer0 input projection [t][col][b]
__device__ float g_h0[(size_t)TT * UU * BB];    // [t][u][b]
__device__ float g_h1[(size_t)TT * UU * BB];
__device__ float g_h2[(size_t)TT * UU * BB];
__device__ unsigned g_flags[NCTA];              // zero-init, monotonic barrier counters

// ---------------- helpers ----------------------------------------------------
__device__ __forceinline__ unsigned ld_acq(const unsigned* p) {
    unsigned v;
    asm volatile("ld.acquire.gpu.u32 %0, [%1];" : "=r"(v) : "l"(p) : "memory");
    return v;
}
__device__ __forceinline__ void st_rel(unsigned* p, unsigned v) {
    asm volatile("st.release.gpu.u32 [%0], %1;" :: "l"(p), "r"(v) : "memory");
}
__device__ __forceinline__ void ffma2(ull& d, ull a, ull b) {
    asm("fma.rn.f32x2 %0, %1, %2, %0;" : "+l"(d) : "l"(a), "l"(b));
}
__device__ __forceinline__ ull add2(ull a, ull b) {
    ull r; asm("add.rn.f32x2 %0, %1, %2;" : "=l"(r) : "l"(a), "l"(b)); return r;
}
__device__ __forceinline__ ull dup2(float w) {
    ull r; asm("mov.b64 %0, {%1, %1};" : "=l"(r) : "f"(w)); return r;
}
__device__ __forceinline__ ull pack2(float lo, float hi) {
    ull r; asm("mov.b64 %0, {%1, %2};" : "=l"(r) : "f"(lo), "f"(hi)); return r;
}
__device__ __forceinline__ float f2lo(ull v){ return __int_as_float((int)(unsigned)v); }
__device__ __forceinline__ float f2hi(ull v){ return __int_as_float((int)(v >> 32)); }
__device__ __forceinline__ float sigm(float x) { return 1.0f / (1.0f + __expf(-x)); }

// ---------------- layer-0 input projection (K = F = 3) -----------------------
__global__ void xp_l0_kernel(const float* __restrict__ x,
                             const float* __restrict__ Wx0,
                             const float* __restrict__ b0)
{
    int t = blockIdx.x;
    __shared__ float xs[BB * FF];
    __shared__ float ws[FF * GG];
    __shared__ float bs[GG];
    int tid = threadIdx.x;
    if (tid < BB * FF) {
        int b = tid / FF, d = tid % FF;
        xs[tid] = x[(size_t)b * (TT * FF) + t * FF + d];
    }
    for (int i = tid; i < FF * GG; i += 256) ws[i] = Wx0[i];
    for (int i = tid; i < GG; i += 256) bs[i] = b0[i];
    __syncthreads();
    float* dst = g_xp + (size_t)t * GG * BB;
    for (int idx = tid; idx < GG * BB; idx += 256) {
        int col = idx >> 6, b = idx & 63;
        float v = bs[col]
                + xs[b * 3 + 0] * ws[col]
                + xs[b * 3 + 1] * ws[GG + col]
                + xs[b * 3 + 2] * ws[2 * GG + col];
        dst[idx] = v;
    }
}

// ---------------- fused 3-layer wavefront, full-CTA jobs ----------------------
// 148 CTAs x 256 threads, persistent, 702 steps, one grid barrier per step.
// Job table (perfectly balanced, 22400 col·k per CTA):
//   cta   0..29 : L0, 14 units (pad u>=400), k=400.  2 k-slices x 4 warps.
//   cta  30..88 : L1,  7 units (pad),        k=800.  4 k-slices x 2 warps.
//   cta 89..147 : L2,  7 units (pad),        k=800.  4 k-slices x 2 warps.
// Thread = 14 cols x 1 batch-pair x 200 k-rows  (2800 FFMA2/step, all warps).
// smem: weights (pre-dup'd f32x2) 179200 B + reduce 28672 B = 207872 B.
#define WSM_BYTES 179200
#define WAVE_SMEM (WSM_BYTES + 28672)

template<int NCOLS>
__device__ __forceinline__ void accum200(ull (&acc)[14],
                                         const ull* __restrict__ wrow,
                                         const float* __restrict__ hsrc,
                                         int lane)
{
    const char* hp = (const char*)(hsrc + lane * 2);   // this thread's pair
    ull h[8], hn[8];
#pragma unroll
    for (int j = 0; j < 8; j++) h[j] = *(const ull*)(hp + j * (BB * 4));
#pragma unroll 1
    for (int r = 0; r < 200; r += 8) {
        if (r + 8 < 200) {
#pragma unroll
            for (int j = 0; j < 8; j++)
                hn[j] = *(const ull*)(hp + (r + 8 + j) * (BB * 4));
        }
#pragma unroll
        for (int j = 0; j < 8; j++) {
            const ull* w = wrow + (size_t)(r + j) * NCOLS;
#pragma unroll
            for (int c = 0; c < 14; c += 2) {
                ulonglong2 w2 = *(const ulonglong2*)(w + c);   // broadcast LDS.128
                ffma2(acc[c],     h[j], w2.x);
                ffma2(acc[c + 1], h[j], w2.y);
            }
        }
#pragma unroll
        for (int j = 0; j < 8; j++) h[j] = hn[j];
    }
}

// LSTM cell, one unit, two batches; z packed f32x2 per gate; c in-place.
__device__ __forceinline__ void cell2(const ull z[4], float& c0, float& c1,
                                      float piv, float pfv, float pov,
                                      float* __restrict__ outp)
{
    float zi0 = f2lo(z[0]), zi1 = f2hi(z[0]);
    float zf0 = f2lo(z[1]), zf1 = f2hi(z[1]);
    float zg0 = f2lo(z[2]), zg1 = f2hi(z[2]);
    float zo0 = f2lo(z[3]), zo1 = f2hi(z[3]);

    float i0 = sigm(zi0 + piv * c0);
    float f0 = sigm(zf0 + pfv * c0);
    float cn0 = f0 * c0 + i0 * tanhf(zg0);
    float o0 = sigm(zo0 + pov * cn0);
    float h0 = o0 * tanhf(cn0);
    c0 = cn0;

    float i1 = sigm(zi1 + piv * c1);
    float f1 = sigm(zf1 + pfv * c1);
    float cn1 = f1 * c1 + i1 * tanhf(zg1);
    float o1 = sigm(zo1 + pov * cn1);
    float h1 = o1 * tanhf(cn1);
    c1 = cn1;

    *(ull*)outp = pack2(h0, h1);
}

__global__ void __launch_bounds__(256, 1) wave_kernel(const float* __restrict__ Wx1,
                                                      const float* __restrict__ Wx2,
                                                      const float* __restrict__ Wh,
                                                      const float* __restrict__ bb,
                                                      const float* __restrict__ pi,
                                                      const float* __restrict__ pf,
                                                      const float* __restrict__ po)
{
    extern __shared__ char smraw[];
    ull*   w2s = (ull*)smraw;                    // [k][ncols] pre-dup'd pairs
    float* red = (float*)(smraw + WSM_BYTES);    // [nslice][ncols][64]

    const int tid  = threadIdx.x;
    const int cta  = blockIdx.x;
    const int wid  = tid >> 5;
    const int lane = tid & 31;

    int jtype, ubase, nu;
    if (cta < 30)      { jtype = 0; ubase = cta * 14;        nu = 14; }
    else if (cta < 89) { jtype = 1; ubase = (cta - 30) * 7;  nu = 7;  }
    else               { jtype = 2; ubase = (cta - 89) * 7;  nu = 7;  }
    const int ncols  = nu * 4;                 // 56 or 28
    const int nslice = (jtype == 0) ? 2 : 4;
    const int nslots = (jtype == 0) ? 2 : 1;

    // ---- weight fill: 22400 pre-duplicated f32x2 pairs ----
    {
        const float* Wh0 = Wh;
        const float* Wh1 = Wh + (size_t)UU * GG;
        const float* Wh2 = Wh + (size_t)2 * UU * GG;
        for (int idx = tid; idx < 22400; idx += 256) {
            int r = idx / ncols, col = idx - r * ncols;
            int ul = col >> 2, g = col & 3, u = ubase + ul;
            float v = 0.f;
            if (u < UU) {
                const float* W; int k2 = r;
                if (jtype == 0) { W = Wh0; }
                else if (jtype == 1) { if (r < 400) W = Wx1; else { W = Wh1; k2 = r - 400; } }
                else                 { if (r < 400) W = Wx2; else { W = Wh2; k2 = r - 400; } }
                v = W[(size_t)k2 * GG + g * UU + u];
            }
            w2s[idx] = dup2(v);    // idx == r*ncols + col
        }
    }

    // ---- gate-cell constants (<=2 register-resident cells per thread) ----
    float pi_r[2], pf_r[2], po_r[2];
    ull   bz[2][4];
    float cc[2][2];
    int   cu[2], cpb[2];
    bool  cok[2];
#pragma unroll
    for (int q = 0; q < 2; q++) {
        cok[q] = false; cu[q] = 0; cpb[q] = 0;
        pi_r[q] = pf_r[q] = po_r[q] = 0.f;
        bz[q][0] = bz[q][1] = bz[q][2] = bz[q][3] = 0ull;
        cc[q][0] = cc[q][1] = 0.f;
        int cell = tid + q * 256;
        if (q < nslots && cell < nu * 32) {
            int ul = cell >> 5, pb = cell & 31, u = ubase + ul;
            cu[q] = u; cpb[q] = pb;
            if (u < UU) {
                cok[q] = true;
                pi_r[q] = pi[jtype * UU + u];
                pf_r[q] = pf[jtype * UU + u];
                po_r[q] = po[jtype * UU + u];
                if (jtype > 0)
                    for (int g = 0; g < 4; g++)
                        bz[q][g] = dup2(bb[jtype * GG + g * UU + u]);
            }
        }
    }

    // ---- compute-thread mapping ----
    int sl, wo;
    if (jtype == 0) { sl = wid >> 2; wo = wid & 3; }
    else            { sl = wid >> 1; wo = wid & 1; }
    const int c0 = wo * 14;
    const ull* wrow = w2s + (size_t)sl * 200 * ncols + c0;

    const unsigned base = g_flags[cta];
    __syncthreads();

    for (int s = 0; s < NSTEPS; s++) {
        const int t = s - jtype;
        const bool act = (t >= 0) && (t < TT);

        // z init: xp prefetch (L0) or bias (L1/2) — overlaps with compute
        ull zin[2][4];
        if (act) {
#pragma unroll
            for (int q = 0; q < 2; q++) {
                if (q < nslots && cok[q]) {
                    if (jtype == 0) {
                        const float* xpp = g_xp + ((size_t)t * GG + cu[q]) * BB + 2 * cpb[q];
                        zin[q][0] = __ldg((const ull*)xpp);
                        zin[q][1] = __ldg((const ull*)(xpp + (size_t)UU * BB));
                        zin[q][2] = __ldg((const ull*)(xpp + (size_t)2 * UU * BB));
                        zin[q][3] = __ldg((const ull*)(xpp + (size_t)3 * UU * BB));
                    } else {
#pragma unroll
                        for (int g = 0; g < 4; g++) zin[q][g] = bz[q][g];
                    }
                }
            }
        }

        ull acc[14];
#pragma unroll
        for (int c = 0; c < 14; c++) acc[c] = 0ull;

        if (act) {
            const float* hsrc = nullptr;
            if (jtype == 0) {
                if (t > 0) hsrc = g_h0 + ((size_t)(t - 1) * UU + sl * 200) * BB;
            } else {
                if (sl < 2) {
                    hsrc = ((jtype == 1) ? g_h0 : g_h1) + ((size_t)t * UU + sl * 200) * BB;
                } else if (t > 0) {
                    hsrc = ((jtype == 1) ? g_h1 : g_h2) + ((size_t)(t - 1) * UU + (sl - 2) * 200) * BB;
                }
            }
            if (hsrc) {
                if (jtype == 0) accum200<56>(acc, wrow, hsrc, lane);
                else            accum200<28>(acc, wrow, hsrc, lane);
            }
            // store partials (zeros when slice inactive — gate sums all slices)
#pragma unroll
            for (int c = 0; c < 14; c++)
                *(ull*)(red + ((size_t)(sl * ncols) + (c0 + c)) * BB + 2 * lane) = acc[c];
        }
        __syncthreads();

        // gate phase: all 256 threads, register-resident cells
        if (act) {
#pragma unroll
            for (int q = 0; q < 2; q++) {
                if (q < nslots && cok[q]) {
                    int ul4 = (cu[q] - ubase) << 2;
                    ull z[4];
#pragma unroll
                    for (int g = 0; g < 4; g++) {
                        ull zz = zin[q][g];
                        for (int s2 = 0; s2 < nslice; s2++) {
                            ull v = *(const ull*)(red + ((size_t)(s2 * ncols) + (ul4 + g)) * BB + 2 * cpb[q]);
                            zz = add2(zz, v);
                        }
                        z[g] = zz;
                    }
                    float* hout = ((jtype == 0) ? g_h0 : (jtype == 1) ? g_h1 : g_h2)
                                  + ((size_t)t * UU + cu[q]) * BB + 2 * cpb[q];
                    cell2(z, cc[q][0], cc[q][1], pi_r[q], pf_r[q], po_r[q], hout);
                }
            }
        }
        __syncthreads();   // all CTA stores done before release

        if (s < NSTEPS - 1) {
            unsigned tgt = base + (unsigned)s + 1u;
            if (tid == 0) st_rel(&g_flags[cta], tgt);
            if (tid < 32) {
                for (;;) {
                    bool ok = true;
                    for (int i = lane; i < NCTA; i += 32)
                        if (ld_acq(&g_flags[i]) < tgt) ok = false;
                    if (__all_sync(0xffffffffu, ok)) break;
                    __nanosleep(32);
                }
            }
            __syncthreads();
        }
    }
}

// ---------------- final projection ------------------------------------------
// out[b][t][f] = bd[f] + sum_u h2[t][u][b] * Wd[u][f]
__global__ void final_kernel(const float* __restrict__ Wd,
                             const float* __restrict__ bd,
                             float* __restrict__ out)
{
    int t = blockIdx.x;
    int tid = threadIdx.x;  // 192
    __shared__ float wds[UU * FF];
    for (int i = tid; i < UU * FF; i += 192) wds[i] = Wd[i];
    __syncthreads();
    int b = tid / FF, f = tid % FF;
    const float* h = g_h2 + (size_t)t * UU * BB;
    float acc = bd[f];
#pragma unroll 4
    for (int u = 0; u < UU; u++)
        acc += h[(size_t)u * BB + b] * wds[u * FF + f];
    out[(size_t)b * (TT * FF) + t * FF + f] = acc;
}

// ---------------- launch -----------------------------------------------------
extern "C" void kernel_launch(void* const* d_in, const int* in_sizes, int n_in,
                              void* d_out, int out_size)
{
    (void)in_sizes; (void)n_in; (void)out_size;
    const float* x   = (const float*)d_in[0];
    const float* Wx0 = (const float*)d_in[1];
    const float* Wx1 = (const float*)d_in[2];
    const float* Wx2 = (const float*)d_in[3];
    const float* Wh  = (const float*)d_in[4];
    const float* bb  = (const float*)d_in[5];
    const float* pi  = (const float*)d_in[6];
    const float* pf  = (const float*)d_in[7];
    const float* po  = (const float*)d_in[8];
    const float* Wd  = (const float*)d_in[9];
    const float* bd  = (const float*)d_in[10];
    float* out = (float*)d_out;

    cudaFuncSetAttribute(wave_kernel, cudaFuncAttributeMaxDynamicSharedMemorySize, WAVE_SMEM);

    // layer-0 input projection (K=3, fully parallel over t)
    xp_l0_kernel<<<TT, 256>>>(x, Wx0, bb);
    // fused 3-layer wavefront (702 steps, one grid barrier per step, all warps hot)
    wave_kernel<<<NCTA, 256, WAVE_SMEM>>>(Wx1, Wx2, Wh, bb, pi, pf, po);
    // output projection
    final_kernel<<<TT, 192>>>(Wd, bd, out);
}

// round 11
// speedup vs baseline: 1.9096x; 1.1420x over previous
#include <cuda_runtime.h>
#include <cstdint>
#include <cstddef>

// Problem dims
#define TT 700
#define BB 64
#define UU 400
#define GG 1600   // 4*U
#define FF 3
#define NSTEPS 702    // wavefront: L0@s, L1@s-1, L2@s-2
#define NCTA_W 125    // 25 L0 (16 units) + 50 L1 (8 units) + 50 L2 (8 units)

typedef unsigned long long ull;

// ---------------- static device scratch -------------------------------------
__device__ float g_xp[(size_t)TT * GG * BB];    // layer0 input projection [t][col][b]
__device__ float g_h0[(size_t)TT * UU * BB];    // [t][u][b]
__device__ float g_h1[(size_t)TT * UU * BB];
__device__ float g_h2[(size_t)TT * UU * BB];
__device__ unsigned g_flags[NCTA_W];            // zero-init, monotonic barrier counters

// ---------------- helpers ----------------------------------------------------
__device__ __forceinline__ unsigned ld_acq(const unsigned* p) {
    unsigned v;
    asm volatile("ld.acquire.gpu.u32 %0, [%1];" : "=r"(v) : "l"(p) : "memory");
    return v;
}
__device__ __forceinline__ void st_rel(unsigned* p, unsigned v) {
    asm volatile("st.release.gpu.u32 [%0], %1;" :: "l"(p), "r"(v) : "memory");
}
__device__ __forceinline__ void ffma2(ull& d, ull a, ull b) {
    asm("fma.rn.f32x2 %0, %1, %2, %0;" : "+l"(d) : "l"(a), "l"(b));
}
__device__ __forceinline__ ull add2(ull a, ull b) {
    ull r; asm("add.rn.f32x2 %0, %1, %2;" : "=l"(r) : "l"(a), "l"(b)); return r;
}
__device__ __forceinline__ ull dup2(float w) {
    ull r; asm("mov.b64 %0, {%1, %1};" : "=l"(r) : "f"(w)); return r;
}
__device__ __forceinline__ ull pack2(float lo, float hi) {
    ull r; asm("mov.b64 %0, {%1, %2};" : "=l"(r) : "f"(lo), "f"(hi)); return r;
}
__device__ __forceinline__ float f2lo(ull v){ return __int_as_float((int)(unsigned)v); }
__device__ __forceinline__ float f2hi(ull v){ return __int_as_float((int)(v >> 32)); }
__device__ __forceinline__ float sigm(float x) { return 1.0f / (1.0f + __expf(-x)); }

// ---------------- layer-0 input projection (K = F = 3) -----------------------
__global__ void xp_l0_kernel(const float* __restrict__ x,
                             const float* __restrict__ Wx0,
                             const float* __restrict__ b0)
{
    int t = blockIdx.x;
    __shared__ float xs[BB * FF];
    __shared__ float ws[FF * GG];
    __shared__ float bs[GG];
    int tid = threadIdx.x;
    if (tid < BB * FF) {
        int b = tid / FF, d = tid % FF;
        xs[tid] = x[(size_t)b * (TT * FF) + t * FF + d];
    }
    for (int i = tid; i < FF * GG; i += 256) ws[i] = Wx0[i];
    for (int i = tid; i < GG; i += 256) bs[i] = b0[i];
    __syncthreads();
    float* dst = g_xp + (size_t)t * GG * BB;
    for (int idx = tid; idx < GG * BB; idx += 256) {
        int col = idx >> 6, b = idx & 63;
        float v = bs[col]
                + xs[b * 3 + 0] * ws[col]
                + xs[b * 3 + 1] * ws[GG + col]
                + xs[b * 3 + 2] * ws[2 * GG + col];
        dst[idx] = v;
    }
}

// ---------------- fused 3-layer wavefront -------------------------------------
// 125 CTAs x 256 threads, persistent, 702 steps, one grid barrier per step.
// Job table (all CTAs exactly 25,600 col·k, zero padding):
//   cta  0..24 : L0, 16 units (64 cols), k=400.  2 col-halves x 4 k-slices(100).
//   cta 25..74 : L1,  8 units (32 cols), k=800.  8 k-slices(100).
//   cta 75..124: L2,  8 units (32 cols), k=800.  8 k-slices(100).
// Warp = 32 cols x 64 batches x 100 k-rows. Lane = (cg 0..3, pg 0..7).
// Thread = C=8 cols x B=4 batch-pairs: per k-row 2 wLDS.128 + 8 dup + 2 hLDG.128
// + 32 FFMA2. h direct from L2 with 4-row register double-buffer.
// smem: w fp32 [krows][ncols] 102400 B + red 65536 B = 167936 B.
#define WSM_BYTES 102400
#define WAVE_SMEM (WSM_BYTES + 65536)

template<int NC>   // 64 (L0) or 32 (L1/2)
__device__ __forceinline__ void accum100(ull (&acc)[8][4],
                                         const float* __restrict__ wrow0,
                                         const float* __restrict__ hsrc,
                                         int pg)
{
    const char* hp = (const char*)hsrc + pg * 32;   // this thread's 4 pairs
    ulonglong2 hb[2][4][2];                          // [buf][row][half]
#pragma unroll
    for (int j = 0; j < 4; j++) {
        hb[0][j][0] = *(const ulonglong2*)(hp + j * 256);
        hb[0][j][1] = *(const ulonglong2*)(hp + j * 256 + 16);
    }
    const float* wrow = wrow0;
#pragma unroll 2
    for (int rc = 0; rc < 100; rc += 4) {
        int cur = (rc >> 2) & 1;
        if (rc < 96) {
            int nxt = cur ^ 1;
#pragma unroll
            for (int j = 0; j < 4; j++) {
                hb[nxt][j][0] = *(const ulonglong2*)(hp + (rc + 4 + j) * 256);
                hb[nxt][j][1] = *(const ulonglong2*)(hp + (rc + 4 + j) * 256 + 16);
            }
        }
#pragma unroll
        for (int j = 0; j < 4; j++) {
            float4 wa = *(const float4*)(wrow);
            float4 wb = *(const float4*)(wrow + 4);
            ull w0 = dup2(wa.x), w1 = dup2(wa.y), w2 = dup2(wa.z), w3 = dup2(wa.w);
            ull w4 = dup2(wb.x), w5 = dup2(wb.y), w6 = dup2(wb.z), w7 = dup2(wb.w);
            ulonglong2 hA = hb[cur][j][0];
            ulonglong2 hB = hb[cur][j][1];
            ffma2(acc[0][0], hA.x, w0); ffma2(acc[0][1], hA.y, w0);
            ffma2(acc[0][2], hB.x, w0); ffma2(acc[0][3], hB.y, w0);
            ffma2(acc[1][0], hA.x, w1); ffma2(acc[1][1], hA.y, w1);
            ffma2(acc[1][2], hB.x, w1); ffma2(acc[1][3], hB.y, w1);
            ffma2(acc[2][0], hA.x, w2); ffma2(acc[2][1], hA.y, w2);
            ffma2(acc[2][2], hB.x, w2); ffma2(acc[2][3], hB.y, w2);
            ffma2(acc[3][0], hA.x, w3); ffma2(acc[3][1], hA.y, w3);
            ffma2(acc[3][2], hB.x, w3); ffma2(acc[3][3], hB.y, w3);
            ffma2(acc[4][0], hA.x, w4); ffma2(acc[4][1], hA.y, w4);
            ffma2(acc[4][2], hB.x, w4); ffma2(acc[4][3], hB.y, w4);
            ffma2(acc[5][0], hA.x, w5); ffma2(acc[5][1], hA.y, w5);
            ffma2(acc[5][2], hB.x, w5); ffma2(acc[5][3], hB.y, w5);
            ffma2(acc[6][0], hA.x, w6); ffma2(acc[6][1], hA.y, w6);
            ffma2(acc[6][2], hB.x, w6); ffma2(acc[6][3], hB.y, w6);
            ffma2(acc[7][0], hA.x, w7); ffma2(acc[7][1], hA.y, w7);
            ffma2(acc[7][2], hB.x, w7); ffma2(acc[7][3], hB.y, w7);
            wrow += NC;
        }
    }
}

// LSTM cell, one unit, two batches; z packed f32x2 per gate; c in-place.
__device__ __forceinline__ void cell2(const ull z[4], float& c0, float& c1,
                                      float piv, float pfv, float pov,
                                      float* __restrict__ outp)
{
    float zi0 = f2lo(z[0]), zi1 = f2hi(z[0]);
    float zf0 = f2lo(z[1]), zf1 = f2hi(z[1]);
    float zg0 = f2lo(z[2]), zg1 = f2hi(z[2]);
    float zo0 = f2lo(z[3]), zo1 = f2hi(z[3]);

    float i0 = sigm(zi0 + piv * c0);
    float f0 = sigm(zf0 + pfv * c0);
    float cn0 = f0 * c0 + i0 * tanhf(zg0);
    float o0 = sigm(zo0 + pov * cn0);
    float h0 = o0 * tanhf(cn0);
    c0 = cn0;

    float i1 = sigm(zi1 + piv * c1);
    float f1 = sigm(zf1 + pfv * c1);
    float cn1 = f1 * c1 + i1 * tanhf(zg1);
    float o1 = sigm(zo1 + pov * cn1);
    float h1 = o1 * tanhf(cn1);
    c1 = cn1;

    *(ull*)outp = pack2(h0, h1);
}

__global__ void __launch_bounds__(256, 1) wave_kernel(const float* __restrict__ Wx1,
                                                      const float* __restrict__ Wx2,
                                                      const float* __restrict__ Wh,
                                                      const float* __restrict__ bb,
                                                      const float* __restrict__ pi,
                                                      const float* __restrict__ pf,
                                                      const float* __restrict__ po)
{
    extern __shared__ char smraw[];
    float* wsm = (float*)smraw;                  // [krows][ncols] fp32
    ull*   red = (ull*)(smraw + WSM_BYTES);      // [nslice][ncolsTot][32 pairs]

    const int tid  = threadIdx.x;
    const int cta  = blockIdx.x;
    const int wid  = tid >> 5;
    const int lane = tid & 31;
    const int cg   = lane & 3;     // col-group (8 cols)
    const int pg   = lane >> 2;    // pair-group (4 pairs)

    int jtype, ubase, nu;
    if (cta < 25)      { jtype = 0; ubase = cta * 16;        nu = 16; }
    else if (cta < 75) { jtype = 1; ubase = (cta - 25) * 8;  nu = 8;  }
    else               { jtype = 2; ubase = (cta - 75) * 8;  nu = 8;  }
    const int ncols  = nu * 4;                  // 64 or 32
    const int nslice = (jtype == 0) ? 4 : 8;

    const float* Wh0 = Wh;
    const float* Wh1 = Wh + (size_t)UU * GG;
    const float* Wh2 = Wh + (size_t)2 * UU * GG;

    // ---- weight fill: 25600 fp32 ----
    for (int idx = tid; idx < 25600; idx += 256) {
        int k, c;
        if (jtype == 0) { k = idx >> 6; c = idx & 63; }
        else            { k = idx >> 5; c = idx & 31; }
        int ul = c >> 2, g = c & 3, u = ubase + ul;
        float v;
        if (jtype == 0)      v = Wh0[(size_t)k * GG + g * UU + u];
        else if (jtype == 1) v = (k < 400) ? Wx1[(size_t)k * GG + g * UU + u]
                                           : Wh1[(size_t)(k - 400) * GG + g * UU + u];
        else                 v = (k < 400) ? Wx2[(size_t)k * GG + g * UU + u]
                                           : Wh2[(size_t)(k - 400) * GG + g * UU + u];
        wsm[idx] = v;
    }

    // ---- gate-cell constants (1 or 2 cells per thread, all valid) ----
    const int nslots = (jtype == 0) ? 2 : 1;
    float pi_r[2], pf_r[2], po_r[2];
    ull   bz[2][4];
    float cc[2][2];
    int   cu[2], cpb[2];
#pragma unroll
    for (int q = 0; q < 2; q++) {
        cu[q] = ubase; cpb[q] = 0;
        pi_r[q] = pf_r[q] = po_r[q] = 0.f;
        bz[q][0] = bz[q][1] = bz[q][2] = bz[q][3] = 0ull;
        cc[q][0] = cc[q][1] = 0.f;
        if (q < nslots) {
            int cell = tid + q * 256;
            int ul = cell >> 5, pb = cell & 31, u = ubase + ul;
            cu[q] = u; cpb[q] = pb;
            pi_r[q] = pi[jtype * UU + u];
            pf_r[q] = pf[jtype * UU + u];
            po_r[q] = po[jtype * UU + u];
            if (jtype > 0)
                for (int g = 0; g < 4; g++)
                    bz[q][g] = dup2(bb[jtype * GG + g * UU + u]);
        }
    }

    // ---- compute-warp mapping ----
    int sl, chalf;
    if (jtype == 0) { chalf = wid >> 2; sl = wid & 3; }   // 2 halves x 4 slices
    else            { chalf = 0;        sl = wid;     }   // 8 slices
    const int mycol0 = chalf * 32 + cg * 8;
    const float* wrow0 = wsm + (size_t)(sl * 100) * ncols + mycol0;

    const unsigned base = g_flags[cta];
    __syncthreads();

    for (int s = 0; s < NSTEPS; s++) {
        const int t = s - jtype;
        const bool act = (t >= 0) && (t < TT);

        // z init: xp prefetch (L0) or bias (L1/2)
        ull zin[2][4];
        if (act) {
#pragma unroll
            for (int q = 0; q < 2; q++) {
                if (q < nslots) {
                    if (jtype == 0) {
                        const float* xpp = g_xp + ((size_t)t * GG + cu[q]) * BB + 2 * cpb[q];
                        zin[q][0] = __ldg((const ull*)xpp);
                        zin[q][1] = __ldg((const ull*)(xpp + (size_t)UU * BB));
                        zin[q][2] = __ldg((const ull*)(xpp + (size_t)2 * UU * BB));
                        zin[q][3] = __ldg((const ull*)(xpp + (size_t)3 * UU * BB));
                    } else {
#pragma unroll
                        for (int g = 0; g < 4; g++) zin[q][g] = bz[q][g];
                    }
                }
            }
        }

        ull acc[8][4];
#pragma unroll
        for (int c = 0; c < 8; c++)
#pragma unroll
            for (int p = 0; p < 4; p++) acc[c][p] = 0ull;

        if (act) {
            const float* hsrc = nullptr;
            if (jtype == 0) {
                if (t > 0) hsrc = g_h0 + ((size_t)(t - 1) * UU + sl * 100) * BB;
            } else {
                if (sl < 4) {
                    hsrc = ((jtype == 1) ? g_h0 : g_h1) + ((size_t)t * UU + sl * 100) * BB;
                } else if (t > 0) {
                    hsrc = ((jtype == 1) ? g_h1 : g_h2) + ((size_t)(t - 1) * UU + (sl - 4) * 100) * BB;
                }
            }
            if (hsrc) {
                if (jtype == 0) accum100<64>(acc, wrow0, hsrc, pg);
                else            accum100<32>(acc, wrow0, hsrc, pg);
            }
            // partial-sum store: red[sl][col][pair], ull elements
            const int ncolsTot = (jtype == 0) ? 64 : 32;
            ull* rp = red + ((size_t)sl * ncolsTot + mycol0) * 32 + pg * 4;
#pragma unroll
            for (int c = 0; c < 8; c++) {
                ulonglong2 s0; s0.x = acc[c][0]; s0.y = acc[c][1];
                ulonglong2 s1; s1.x = acc[c][2]; s1.y = acc[c][3];
                *(ulonglong2*)(rp + (size_t)c * 32)     = s0;
                *(ulonglong2*)(rp + (size_t)c * 32 + 2) = s1;
            }
        }
        __syncthreads();

        // gate phase: register-resident cells
        if (act) {
            const int ncolsTot = (jtype == 0) ? 64 : 32;
#pragma unroll
            for (int q = 0; q < 2; q++) {
                if (q < nslots) {
                    int ul4 = (cu[q] - ubase) << 2;
                    ull z[4];
#pragma unroll
                    for (int g = 0; g < 4; g++) {
                        ull zz = zin[q][g];
                        for (int s2 = 0; s2 < nslice; s2++)
                            zz = add2(zz, red[((size_t)s2 * ncolsTot + ul4 + g) * 32 + cpb[q]]);
                        z[g] = zz;
                    }
                    float* hout = ((jtype == 0) ? g_h0 : (jtype == 1) ? g_h1 : g_h2)
                                  + ((size_t)t * UU + cu[q]) * BB + 2 * cpb[q];
                    cell2(z, cc[q][0], cc[q][1], pi_r[q], pf_r[q], po_r[q], hout);
                }
            }
        }
        __syncthreads();   // all CTA stores done before release

        if (s < NSTEPS - 1) {
            unsigned tgt = base + (unsigned)s + 1u;
            if (tid == 0) st_rel(&g_flags[cta], tgt);
            if (tid < 32) {
                for (;;) {
                    bool ok = true;
                    for (int i = lane; i < NCTA_W; i += 32)
                        if (ld_acq(&g_flags[i]) < tgt) ok = false;
                    if (__all_sync(0xffffffffu, ok)) break;
                    __nanosleep(32);
                }
            }
            __syncthreads();
        }
    }
}

// ---------------- final projection ------------------------------------------
__global__ void final_kernel(const float* __restrict__ Wd,
                             const float* __restrict__ bd,
                             float* __restrict__ out)
{
    int t = blockIdx.x;
    int tid = threadIdx.x;  // 192
    __shared__ float wds[UU * FF];
    for (int i = tid; i < UU * FF; i += 192) wds[i] = Wd[i];
    __syncthreads();
    int b = tid / FF, f = tid % FF;
    const float* h = g_h2 + (size_t)t * UU * BB;
    float acc = bd[f];
#pragma unroll 4
    for (int u = 0; u < UU; u++)
        acc += h[(size_t)u * BB + b] * wds[u * FF + f];
    out[(size_t)b * (TT * FF) + t * FF + f] = acc;
}

// ---------------- launch -----------------------------------------------------
extern "C" void kernel_launch(void* const* d_in, const int* in_sizes, int n_in,
                              void* d_out, int out_size)
{
    (void)in_sizes; (void)n_in; (void)out_size;
    const float* x   = (const float*)d_in[0];
    const float* Wx0 = (const float*)d_in[1];
    const float* Wx1 = (const float*)d_in[2];
    const float* Wx2 = (const float*)d_in[3];
    const float* Wh  = (const float*)d_in[4];
    const float* bb  = (const float*)d_in[5];
    const float* pi  = (const float*)d_in[6];
    const float* pf  = (const float*)d_in[7];
    const float* po  = (const float*)d_in[8];
    const float* Wd  = (const float*)d_in[9];
    const float* bd  = (const float*)d_in[10];
    float* out = (float*)d_out;

    cudaFuncSetAttribute(wave_kernel, cudaFuncAttributeMaxDynamicSharedMemorySize, WAVE_SMEM);

    // layer-0 input projection (K=3, fully parallel over t)
    xp_l0_kernel<<<TT, 256>>>(x, Wx0, bb);
    // fused 3-layer wavefront (702 steps, one grid barrier per step)
    wave_kernel<<<NCTA_W, 256, WAVE_SMEM>>>(Wx1, Wx2, Wh, bb, pi, pf, po);
    // output projection
    final_kernel<<<TT, 192>>>(Wd, bd, out);
}